// round 7
// baseline (speedup 1.0000x reference)
#include <cuda_runtime.h>
#include <cstdint>

// Problem constants
#define B_    8
#define L_    4096
#define H_    8
#define E_    64
#define WIN   128            // NEIGH
#define QT    256            // queries per block
#define KT    (QT + WIN)     // 384 key rows in SMEM tile
#define NTHR  256
#define SMEM_BYTES (2 * KT * E_ * (int)sizeof(float))   // 196608

// ---- packed f32x2 helpers (sm_100+ PTX; ptxas never auto-fuses these) ----
__device__ __forceinline__ float2 ffma2(float2 a, float2 b, float2 c) {
    float2 r;
    asm("fma.rn.f32x2 %0, %1, %2, %3;"
        : "=l"(reinterpret_cast<unsigned long long&>(r))
        : "l"(reinterpret_cast<unsigned long long&>(a)),
          "l"(reinterpret_cast<unsigned long long&>(b)),
          "l"(reinterpret_cast<unsigned long long&>(c)));
    return r;
}
__device__ __forceinline__ float2 fmul2(float2 a, float2 b) {
    float2 r;
    asm("mul.rn.f32x2 %0, %1, %2;"
        : "=l"(reinterpret_cast<unsigned long long&>(r))
        : "l"(reinterpret_cast<unsigned long long&>(a)),
          "l"(reinterpret_cast<unsigned long long&>(b)));
    return r;
}
__device__ __forceinline__ float ex2(float x) {
    float y;
    asm("ex2.approx.ftz.f32 %0, %1;" : "=f"(y) : "f"(x));
    return y;
}
__device__ __forceinline__ float2 mkf2(float x, float y) { return make_float2(x, y); }

__global__ void __launch_bounds__(NTHR, 1)
local_attn_kernel(const float* __restrict__ Q, const float* __restrict__ K,
                  const float* __restrict__ V, float* __restrict__ O) {
    extern __shared__ float smem[];
    float* Ks = smem;                 // [KT][E_]
    float* Vs = smem + KT * E_;       // [KT][E_]

    const int nqt  = L_ / QT;                      // 16
    const int bid  = blockIdx.x;
    const int b    = bid / (H_ * nqt);
    const int rem  = bid % (H_ * nqt);
    const int h    = rem / nqt;
    const int j    = rem % nqt;
    const int qbase = j * QT;
    const int kbase = qbase - WIN;                 // first key row in tile (may be <0)

    const int tid = threadIdx.x;

    // ---- cooperative K/V tile load (float4, fully coalesced) ----
    {
        const int NV4 = KT * (E_ / 4);             // 6144 float4 per array
        #pragma unroll 4
        for (int idx = tid; idx < NV4; idx += NTHR) {
            int row = idx >> 4;                    // key row in tile
            int c4  = idx & 15;                    // float4 chunk within row
            int kg  = kbase + row;
            float4 kv = make_float4(0.f, 0.f, 0.f, 0.f);
            float4 vv = kv;
            if (kg >= 0) {                         // kg <= qbase+255 <= L-1 always
                size_t g = ((size_t)(b * L_ + kg) * H_ + h) * E_ + (size_t)c4 * 4;
                kv = *reinterpret_cast<const float4*>(K + g);
                vv = *reinterpret_cast<const float4*>(V + g);
            }
            reinterpret_cast<float4*>(Ks)[idx] = kv;
            reinterpret_cast<float4*>(Vs)[idx] = vv;
        }
    }

    // ---- load this thread's query, pre-scaled into exp2 domain ----
    const int q = qbase + tid;
    const float qscale = 0.125f * 1.4426950408889634f;  // (1/sqrt(64)) * log2(e)
    float2 qr[32];
    {
        size_t g = ((size_t)(b * L_ + q) * H_ + h) * E_;
        const float4* qp = reinterpret_cast<const float4*>(Q + g);
        #pragma unroll
        for (int i = 0; i < 16; i++) {
            float4 v = qp[i];
            qr[2 * i    ] = mkf2(v.x * qscale, v.y * qscale);
            qr[2 * i + 1] = mkf2(v.z * qscale, v.w * qscale);
        }
    }
    __syncthreads();

    // ---- online softmax over this warp's key range, 8-key chunks ----
    float2 acc[32];
    #pragma unroll
    for (int i = 0; i < 32; i++) acc[i] = mkf2(0.f, 0.f);
    float m = -1e30f, l = 0.f;

    const int w    = tid >> 5;
    int i_lo = 32 * w + 1;                 // first tile index any lane of this warp needs
    int clampLo = WIN - qbase;             // = 0 - kbase ; >0 only when qbase == 0
    if (clampLo > i_lo) i_lo = clampLo;
    const int i_hi = 32 * w + (31 + WIN);  // last tile index any lane needs (<= 383)

    for (int i0 = i_lo & ~7; i0 <= i_hi; i0 += 8) {
        float s[8];
        #pragma unroll
        for (int kk = 0; kk < 8; kk++) {
            const int i = i0 + kk;
            const float4* kp4 = reinterpret_cast<const float4*>(Ks + i * E_);
            float2 d0 = mkf2(0.f, 0.f), d1 = d0, d2 = d0, d3 = d0;
            #pragma unroll
            for (int e4 = 0; e4 < 16; e4 += 2) {
                float4 k0 = kp4[e4];
                float4 k1 = kp4[e4 + 1];
                d0 = ffma2(qr[2 * e4    ], mkf2(k0.x, k0.y), d0);
                d1 = ffma2(qr[2 * e4 + 1], mkf2(k0.z, k0.w), d1);
                d2 = ffma2(qr[2 * e4 + 2], mkf2(k1.x, k1.y), d2);
                d3 = ffma2(qr[2 * e4 + 3], mkf2(k1.z, k1.w), d3);
            }
            float sv = ((d0.x + d0.y) + (d1.x + d1.y)) + ((d2.x + d2.y) + (d3.x + d3.y));
            int   kg = kbase + i;
            int   dd = q - kg;
            bool  valid = (dd >= 0) && (dd < WIN) && (kg >= 0);
            s[kk] = valid ? sv : -1e30f;
        }

        float cm = s[0];
        #pragma unroll
        for (int kk = 1; kk < 8; kk++) cm = fmaxf(cm, s[kk]);
        float mn   = fmaxf(m, cm);
        float corr = ex2(m - mn);          // both -1e30 -> ex2(0)=1, acc/l are 0 anyway
        m = mn;

        float p[8];
        float ps = 0.f;
        #pragma unroll
        for (int kk = 0; kk < 8; kk++) {
            // guard: fully-masked key must contribute exactly 0 even when m==-1e30
            p[kk] = (s[kk] > -1e29f) ? ex2(s[kk] - m) : 0.f;
            ps += p[kk];
        }
        l = l * corr + ps;

        float2 corr2 = mkf2(corr, corr);
        #pragma unroll
        for (int i2 = 0; i2 < 32; i2++) acc[i2] = fmul2(acc[i2], corr2);

        #pragma unroll
        for (int kk = 0; kk < 8; kk++) {
            const float4* vp4 = reinterpret_cast<const float4*>(Vs + (i0 + kk) * E_);
            float2 pp = mkf2(p[kk], p[kk]);
            #pragma unroll
            for (int e4 = 0; e4 < 16; e4++) {
                float4 v = vp4[e4];
                acc[2 * e4    ] = ffma2(pp, mkf2(v.x, v.y), acc[2 * e4    ]);
                acc[2 * e4 + 1] = ffma2(pp, mkf2(v.z, v.w), acc[2 * e4 + 1]);
            }
        }
    }

    // ---- normalize and store (float4, full-sector writes) ----
    float inv = 1.0f / l;                  // l >= 1 (self key always valid)
    size_t g = ((size_t)(b * L_ + q) * H_ + h) * E_;
    float4* op = reinterpret_cast<float4*>(O + g);
    #pragma unroll
    for (int i = 0; i < 16; i++) {
        float4 o;
        o.x = acc[2 * i    ].x * inv;
        o.y = acc[2 * i    ].y * inv;
        o.z = acc[2 * i + 1].x * inv;
        o.w = acc[2 * i + 1].y * inv;
        op[i] = o;
    }
}

extern "C" void kernel_launch(void* const* d_in, const int* in_sizes, int n_in,
                              void* d_out, int out_size) {
    const float* Q = (const float*)d_in[0];
    const float* K = (const float*)d_in[1];
    const float* V = (const float*)d_in[2];
    float* O = (float*)d_out;

    cudaFuncSetAttribute(local_attn_kernel,
                         cudaFuncAttributeMaxDynamicSharedMemorySize, SMEM_BYTES);

    dim3 grid(B_ * H_ * (L_ / QT));   // 1024 blocks
    dim3 block(NTHR);
    local_attn_kernel<<<grid, block, SMEM_BYTES>>>(Q, K, V, O);
}